// round 1
// baseline (speedup 1.0000x reference)
#include <cuda_runtime.h>

// ---------------------------------------------------------------------------
// WindowAttention (Swin-style), B=16, H=W=128, C=128, WS=4, HEADS=4, hd=32
//   windows: 16 * 32 * 32 = 16384, tokens/window n = 16
//   rows (window-ordered tokens) = 16384*16 = 262144
//
// Pipeline:
//   K1: g_qkv[wr, 0:384] = x[map(wr), :] @ qkv_w + qkv_b      (gather fused)
//   K2: per-window attention (bias + softmax) -> g_att[wr, 0:128]
//   K3: out[map(wr), :] = g_att[wr, :] @ proj_w + proj_b      (scatter fused)
// ---------------------------------------------------------------------------

#define NWIN   16384
#define ROWS   (NWIN * 16)     // 262144
#define CDIM   128
#define QKVN   384

// scratch (device globals: allocation-free per harness rules)
__device__ float g_qkv[(size_t)ROWS * QKVN];   // ~402 MB
__device__ float g_att[(size_t)ROWS * CDIM];   // ~134 MB

// window-ordered row -> row in (B, H*W) token layout (same map both directions)
__device__ __forceinline__ int map_row(int wr) {
    int wid = wr >> 4, t = wr & 15;
    int b   = wid >> 10, rem = wid & 1023;
    int hn  = rem >> 5,  wn  = rem & 31;
    int gy  = (hn << 2) + (t >> 2);
    int gx  = (wn << 2) + (t & 3);
    return (b << 14) + (gy << 7) + gx;          // b*16384 + gy*128 + gx
}

// ---------------------------------------------------------------------------
// K1: QKV GEMM, M=262144 (gathered), N=384, K=128. 64x64 tile, 2 K-stages.
// ---------------------------------------------------------------------------
__global__ __launch_bounds__(256) void k_qkv(const float* __restrict__ x,
                                             const float* __restrict__ w,
                                             const float* __restrict__ bias) {
    __shared__ float As[64][68];   // padded: (4*68)%32 = 16 -> conflict-free
    __shared__ float Bs[64][64];

    const int tid = threadIdx.x;
    const int m0  = blockIdx.x * 64;
    const int n0  = blockIdx.y * 64;
    const int ty  = tid >> 4, tx = tid & 15;
    const int rg  = ty * 4,   cg = tx * 4;

    float acc[4][4] = {};

    for (int kt = 0; kt < 2; kt++) {
        // load A tile: 64 rows x 64 k  (1024 float4)
        #pragma unroll
        for (int i = 0; i < 4; i++) {
            int c  = i * 256 + tid;
            int r  = c >> 4, k4 = c & 15;
            int gr = map_row(m0 + r);
            float4 v = *(const float4*)&x[(size_t)gr * 128 + kt * 64 + k4 * 4];
            *(float4*)&As[r][k4 * 4] = v;
        }
        // load B tile: 64 k x 64 n
        #pragma unroll
        for (int i = 0; i < 4; i++) {
            int c = i * 256 + tid;
            int k = c >> 4, n4 = c & 15;
            float4 v = *(const float4*)&w[(size_t)(kt * 64 + k) * QKVN + n0 + n4 * 4];
            *(float4*)&Bs[k][n4 * 4] = v;
        }
        __syncthreads();

        #pragma unroll 8
        for (int k = 0; k < 64; k++) {
            float a0 = As[rg + 0][k];
            float a1 = As[rg + 1][k];
            float a2 = As[rg + 2][k];
            float a3 = As[rg + 3][k];
            float4 b = *(const float4*)&Bs[k][cg];
            acc[0][0] += a0 * b.x; acc[0][1] += a0 * b.y; acc[0][2] += a0 * b.z; acc[0][3] += a0 * b.w;
            acc[1][0] += a1 * b.x; acc[1][1] += a1 * b.y; acc[1][2] += a1 * b.z; acc[1][3] += a1 * b.w;
            acc[2][0] += a2 * b.x; acc[2][1] += a2 * b.y; acc[2][2] += a2 * b.z; acc[2][3] += a2 * b.w;
            acc[3][0] += a3 * b.x; acc[3][1] += a3 * b.y; acc[3][2] += a3 * b.z; acc[3][3] += a3 * b.w;
        }
        __syncthreads();
    }

    float4 bb = *(const float4*)&bias[n0 + cg];
    #pragma unroll
    for (int i = 0; i < 4; i++) {
        float4 o;
        o.x = acc[i][0] + bb.x;
        o.y = acc[i][1] + bb.y;
        o.z = acc[i][2] + bb.z;
        o.w = acc[i][3] + bb.w;
        *(float4*)&g_qkv[(size_t)(m0 + rg + i) * QKVN + n0 + cg] = o;
    }
}

// ---------------------------------------------------------------------------
// K2: per-window attention. 1 block (64 threads) per window.
// thread = (head, row); full softmax row in registers.
// qkv row layout per token: [q(4 heads x 32) | k(...) | v(...)]
// ---------------------------------------------------------------------------
__global__ __launch_bounds__(64) void k_attn(const float* __restrict__ btbl) {
    __shared__ float s[16 * 384];
    __shared__ float sb[196];          // 49 x 4 bias table

    const int wid = blockIdx.x;
    const int tid = threadIdx.x;

    // load window qkv tile (1536 float4)
    {
        const float4* src = (const float4*)&g_qkv[(size_t)wid * (16 * 384)];
        float4* dst = (float4*)s;
        #pragma unroll
        for (int i = 0; i < 24; i++) dst[i * 64 + tid] = src[i * 64 + tid];
    }
    for (int j = tid; j < 196; j += 64) sb[j] = btbl[j];
    __syncthreads();

    const int h = tid >> 4, r = tid & 15;
    const float scale = 0.17677669529663687f;   // 1/sqrt(32)

    float4 q[8];
    {
        const float4* qp = (const float4*)&s[r * 384 + h * 32];
        #pragma unroll
        for (int d = 0; d < 8; d++) {
            q[d] = qp[d];
            q[d].x *= scale; q[d].y *= scale; q[d].z *= scale; q[d].w *= scale;
        }
    }

    float sc[16];
    float mx = -1e30f;
    #pragma unroll
    for (int m = 0; m < 16; m++) {
        const float4* kp = (const float4*)&s[m * 384 + 128 + h * 32];
        float acc = 0.f;
        #pragma unroll
        for (int d = 0; d < 8; d++) {
            float4 kk = kp[d];
            acc += q[d].x * kk.x + q[d].y * kk.y + q[d].z * kk.z + q[d].w * kk.w;
        }
        int dy = (r >> 2) - (m >> 2) + 3;
        int dx = (r & 3)  - (m & 3)  + 3;
        acc += sb[(dy * 7 + dx) * 4 + h];
        sc[m] = acc;
        mx = fmaxf(mx, acc);
    }

    float sum = 0.f;
    #pragma unroll
    for (int m = 0; m < 16; m++) { sc[m] = expf(sc[m] - mx); sum += sc[m]; }
    const float inv = 1.f / sum;

    float4 o[8] = {};
    #pragma unroll
    for (int m = 0; m < 16; m++) {
        float p = sc[m] * inv;
        const float4* vp = (const float4*)&s[m * 384 + 256 + h * 32];
        #pragma unroll
        for (int d = 0; d < 8; d++) {
            float4 vv = vp[d];
            o[d].x += p * vv.x; o[d].y += p * vv.y; o[d].z += p * vv.z; o[d].w += p * vv.w;
        }
    }

    float4* op = (float4*)&g_att[(size_t)(wid * 16 + r) * 128 + h * 32];
    #pragma unroll
    for (int d = 0; d < 8; d++) op[d] = o[d];
}

// ---------------------------------------------------------------------------
// K3: proj GEMM, M=262144, N=128, K=128, scatter epilogue.
// ---------------------------------------------------------------------------
__global__ __launch_bounds__(256) void k_proj(const float* __restrict__ w,
                                              const float* __restrict__ bias,
                                              float* __restrict__ out) {
    __shared__ float As[64][68];
    __shared__ float Bs[64][64];

    const int tid = threadIdx.x;
    const int m0  = blockIdx.x * 64;
    const int n0  = blockIdx.y * 64;
    const int ty  = tid >> 4, tx = tid & 15;
    const int rg  = ty * 4,   cg = tx * 4;

    float acc[4][4] = {};

    for (int kt = 0; kt < 2; kt++) {
        #pragma unroll
        for (int i = 0; i < 4; i++) {
            int c = i * 256 + tid;
            int r = c >> 4, k4 = c & 15;
            float4 v = *(const float4*)&g_att[(size_t)(m0 + r) * 128 + kt * 64 + k4 * 4];
            *(float4*)&As[r][k4 * 4] = v;
        }
        #pragma unroll
        for (int i = 0; i < 4; i++) {
            int c = i * 256 + tid;
            int k = c >> 4, n4 = c & 15;
            float4 v = *(const float4*)&w[(size_t)(kt * 64 + k) * CDIM + n0 + n4 * 4];
            *(float4*)&Bs[k][n4 * 4] = v;
        }
        __syncthreads();

        #pragma unroll 8
        for (int k = 0; k < 64; k++) {
            float a0 = As[rg + 0][k];
            float a1 = As[rg + 1][k];
            float a2 = As[rg + 2][k];
            float a3 = As[rg + 3][k];
            float4 b = *(const float4*)&Bs[k][cg];
            acc[0][0] += a0 * b.x; acc[0][1] += a0 * b.y; acc[0][2] += a0 * b.z; acc[0][3] += a0 * b.w;
            acc[1][0] += a1 * b.x; acc[1][1] += a1 * b.y; acc[1][2] += a1 * b.z; acc[1][3] += a1 * b.w;
            acc[2][0] += a2 * b.x; acc[2][1] += a2 * b.y; acc[2][2] += a2 * b.z; acc[2][3] += a2 * b.w;
            acc[3][0] += a3 * b.x; acc[3][1] += a3 * b.y; acc[3][2] += a3 * b.z; acc[3][3] += a3 * b.w;
        }
        __syncthreads();
    }

    float4 bb = *(const float4*)&bias[n0 + cg];
    #pragma unroll
    for (int i = 0; i < 4; i++) {
        int gr = map_row(m0 + rg + i);
        float4 o;
        o.x = acc[i][0] + bb.x;
        o.y = acc[i][1] + bb.y;
        o.z = acc[i][2] + bb.z;
        o.w = acc[i][3] + bb.w;
        *(float4*)&out[(size_t)gr * 128 + n0 + cg] = o;
    }
}

// ---------------------------------------------------------------------------
// launch
// inputs: 0:x 1:H 2:W 3:qkv_w 4:qkv_b 5:proj_w 6:proj_b 7:bias_tbl
// ---------------------------------------------------------------------------
extern "C" void kernel_launch(void* const* d_in, const int* in_sizes, int n_in,
                              void* d_out, int out_size) {
    const float* x     = (const float*)d_in[0];
    const float* qkvw  = (const float*)d_in[3];
    const float* qkvb  = (const float*)d_in[4];
    const float* projw = (const float*)d_in[5];
    const float* projb = (const float*)d_in[6];
    const float* btbl  = (const float*)d_in[7];
    float* out = (float*)d_out;

    k_qkv <<<dim3(ROWS / 64, QKVN / 64), 256>>>(x, qkvw, qkvb);
    k_attn<<<NWIN, 64>>>(btbl);
    k_proj<<<dim3(ROWS / 64, CDIM / 64), 256>>>(projw, projb, out);
}

// round 2
// speedup vs baseline: 1.3852x; 1.3852x over previous
#include <cuda_runtime.h>
#include <cuda_bf16.h>
#include <cstdint>

// ---------------------------------------------------------------------------
// WindowAttention (Swin), B=16, H=W=128, C=128, WS=4, HEADS=4, hd=32
// K1: qkv GEMM (bf16x3 split tensor-core), gather fused
// K2: per-window attention (fp32), 2 windows / block
// K3: proj GEMM (bf16x3), scatter fused
// ---------------------------------------------------------------------------

#define NWIN   16384
#define ROWS   (NWIN * 16)     // 262144
#define CDIM   128
#define QKVN   384
#define PITCH  68              // u32 words per smem row (64 bf16-pairs + 4 pad)

__device__ float g_qkv[(size_t)ROWS * QKVN];
__device__ float g_att[(size_t)ROWS * CDIM];

__device__ __forceinline__ int map_row(int wr) {
    int wid = wr >> 4, t = wr & 15;
    int b   = wid >> 10, rem = wid & 1023;
    int hn  = rem >> 5,  wn  = rem & 31;
    int gy  = (hn << 2) + (t >> 2);
    int gx  = (wn << 2) + (t & 3);
    return (b << 14) + (gy << 7) + gx;
}

__device__ __forceinline__ uint32_t pk(__nv_bfloat16 a, __nv_bfloat16 b) {
    uint16_t ua = *(uint16_t*)&a, ub = *(uint16_t*)&b;
    return (uint32_t)ua | ((uint32_t)ub << 16);
}

// split two floats into packed bf16 hi pair + lo pair
__device__ __forceinline__ void split2(float x, float y, uint32_t& hi, uint32_t& lo) {
    __nv_bfloat16 hx = __float2bfloat16_rn(x);
    __nv_bfloat16 hy = __float2bfloat16_rn(y);
    __nv_bfloat16 lx = __float2bfloat16_rn(x - __bfloat162float(hx));
    __nv_bfloat16 ly = __float2bfloat16_rn(y - __bfloat162float(hy));
    hi = pk(hx, hy);
    lo = pk(lx, ly);
}

#define LDSM4(R, addr) \
    asm volatile("ldmatrix.sync.aligned.m8n8.x4.shared.b16 {%0,%1,%2,%3}, [%4];" \
                 : "=r"((R)[0]), "=r"((R)[1]), "=r"((R)[2]), "=r"((R)[3]) : "r"(addr))
#define LDSM2(R, addr) \
    asm volatile("ldmatrix.sync.aligned.m8n8.x2.shared.b16 {%0,%1}, [%2];" \
                 : "=r"((R)[0]), "=r"((R)[1]) : "r"(addr))
#define MMA16816(C, A, B) \
    asm volatile("mma.sync.aligned.m16n8k16.row.col.f32.bf16.bf16.f32 " \
                 "{%0,%1,%2,%3}, {%4,%5,%6,%7}, {%8,%9}, {%0,%1,%2,%3};" \
                 : "+f"((C)[0]), "+f"((C)[1]), "+f"((C)[2]), "+f"((C)[3]) \
                 : "r"((A)[0]), "r"((A)[1]), "r"((A)[2]), "r"((A)[3]), \
                   "r"((B)[0]), "r"((B)[1]))

// generic bf16x3 GEMM block: 128M x 64N, K=128, 4 warps (warp tile 64x32)
// GATHER selects A-row mapping; epilogue differs per kernel.
template <bool GATHER_A, bool SCATTER_OUT>
__device__ __forceinline__ void gemm_body(const float* __restrict__ Asrc, int lda,
                                          const float* __restrict__ Bsrc, int ldb,
                                          const float* __restrict__ bias,
                                          float* __restrict__ Out, int ldo,
                                          int m0, int n0) {
    extern __shared__ uint32_t sm[];
    uint32_t* AH = sm;
    uint32_t* AL = AH + 128 * PITCH;
    uint32_t* BH = AL + 128 * PITCH;
    uint32_t* BL = BH + 64 * PITCH;

    const int tid = threadIdx.x;

    // ---- A tile: 128 rows x 128 K, fp32 -> bf16 hi/lo ----
    #pragma unroll
    for (int it = 0; it < 32; it++) {
        int idx = it * 128 + tid;
        int row = idx >> 5, q = idx & 31;
        int ar = GATHER_A ? map_row(m0 + row) : (m0 + row);
        float4 v = *(const float4*)&Asrc[(size_t)ar * lda + q * 4];
        uint32_t h0, l0, h1, l1;
        split2(v.x, v.y, h0, l0);
        split2(v.z, v.w, h1, l1);
        int base = row * PITCH + q * 2;
        AH[base] = h0; AH[base + 1] = h1;
        AL[base] = l0; AL[base + 1] = l1;
    }

    // ---- B tile: transpose w[k][n0+n] -> Bs[n][k], hi/lo ----
    {
        __nv_bfloat16* BH16 = (__nv_bfloat16*)BH;
        __nv_bfloat16* BL16 = (__nv_bfloat16*)BL;
        #pragma unroll
        for (int it = 0; it < 64; it++) {
            int idx = it * 128 + tid;
            int k = idx >> 6, n = idx & 63;
            float f = Bsrc[(size_t)k * ldb + n0 + n];
            __nv_bfloat16 h = __float2bfloat16_rn(f);
            __nv_bfloat16 l = __float2bfloat16_rn(f - __bfloat162float(h));
            BH16[n * (PITCH * 2) + k] = h;
            BL16[n * (PITCH * 2) + k] = l;
        }
    }
    __syncthreads();

    const int lane = tid & 31, wid = tid >> 5;
    const int row0 = (wid >> 1) * 64;
    const int col0 = (wid & 1) * 32;

    const uint32_t a_r  = lane & 15;
    const uint32_t a_c  = (lane >> 4) << 2;          // 0 or 4
    const uint32_t b_r  = lane & 7;
    const uint32_t b_c  = ((lane >> 3) & 1) << 2;    // 0 or 4

    const uint32_t AHs = (uint32_t)__cvta_generic_to_shared(AH);
    const uint32_t ALs = (uint32_t)__cvta_generic_to_shared(AL);
    const uint32_t BHs = (uint32_t)__cvta_generic_to_shared(BH);
    const uint32_t BLs = (uint32_t)__cvta_generic_to_shared(BL);

    float acc[4][4][4];
    #pragma unroll
    for (int i = 0; i < 4; i++)
        #pragma unroll
        for (int j = 0; j < 4; j++)
            #pragma unroll
            for (int c = 0; c < 4; c++) acc[i][j][c] = 0.f;

    #pragma unroll
    for (int ks = 0; ks < 8; ks++) {
        uint32_t ah[4][4], al[4][4], bh[4][2], bl[4][2];
        #pragma unroll
        for (int mi = 0; mi < 4; mi++) {
            uint32_t off = ((row0 + mi * 16 + a_r) * PITCH + ks * 8 + a_c) * 4;
            LDSM4(ah[mi], AHs + off);
            LDSM4(al[mi], ALs + off);
        }
        #pragma unroll
        for (int ni = 0; ni < 4; ni++) {
            uint32_t off = ((col0 + ni * 8 + b_r) * PITCH + ks * 8 + b_c) * 4;
            LDSM2(bh[ni], BHs + off);
            LDSM2(bl[ni], BLs + off);
        }
        #pragma unroll
        for (int mi = 0; mi < 4; mi++)
            #pragma unroll
            for (int ni = 0; ni < 4; ni++) {
                MMA16816(acc[mi][ni], ah[mi], bh[ni]);
                MMA16816(acc[mi][ni], ah[mi], bl[ni]);
                MMA16816(acc[mi][ni], al[mi], bh[ni]);
            }
    }

    // ---- epilogue ----
    #pragma unroll
    for (int mi = 0; mi < 4; mi++) {
        #pragma unroll
        for (int ni = 0; ni < 4; ni++) {
            int r = m0 + row0 + mi * 16 + (lane >> 2);
            int c = n0 + col0 + ni * 8 + (lane & 3) * 2;
            float b0 = __ldg(&bias[c]), b1 = __ldg(&bias[c + 1]);
            int r0g = SCATTER_OUT ? map_row(r)     : r;
            int r1g = SCATTER_OUT ? map_row(r + 8) : (r + 8);
            float2 o0 = make_float2(acc[mi][ni][0] + b0, acc[mi][ni][1] + b1);
            float2 o1 = make_float2(acc[mi][ni][2] + b0, acc[mi][ni][3] + b1);
            *(float2*)&Out[(size_t)r0g * ldo + c] = o0;
            *(float2*)&Out[(size_t)r1g * ldo + c] = o1;
        }
    }
}

__global__ __launch_bounds__(128) void k_qkv(const float* __restrict__ x,
                                             const float* __restrict__ w,
                                             const float* __restrict__ bias) {
    gemm_body<true, false>(x, CDIM, w, QKVN, bias, g_qkv, QKVN,
                           blockIdx.y * 128, blockIdx.x * 64);
}

__global__ __launch_bounds__(128) void k_proj(const float* __restrict__ w,
                                              const float* __restrict__ bias,
                                              float* __restrict__ out) {
    gemm_body<false, true>(g_att, CDIM, w, CDIM, bias, out, CDIM,
                           blockIdx.y * 128, blockIdx.x * 64);
}

// ---------------------------------------------------------------------------
// K2: attention, 2 windows per 128-thread block; thread = (win, head, row)
// ---------------------------------------------------------------------------
__global__ __launch_bounds__(128) void k_attn(const float* __restrict__ btbl) {
    __shared__ float s[2 * 16 * 384];   // exactly 48 KB

    const int tid = threadIdx.x;
    const int w0  = blockIdx.x * 2;

    {
        const float4* src = (const float4*)&g_qkv[(size_t)w0 * (16 * 384)];
        float4* dst = (float4*)s;
        #pragma unroll
        for (int i = 0; i < 24; i++) dst[i * 128 + tid] = src[i * 128 + tid];
    }
    __syncthreads();

    const int lw = tid >> 6;
    const int h  = (tid >> 4) & 3;
    const int r  = tid & 15;
    const float scale = 0.17677669529663687f;
    float* base = s + lw * 6144;

    float4 q[8];
    {
        const float4* qp = (const float4*)&base[r * 384 + h * 32];
        #pragma unroll
        for (int d = 0; d < 8; d++) {
            q[d] = qp[d];
            q[d].x *= scale; q[d].y *= scale; q[d].z *= scale; q[d].w *= scale;
        }
    }

    float sc[16];
    float mx = -1e30f;
    #pragma unroll
    for (int m = 0; m < 16; m++) {
        const float4* kp = (const float4*)&base[m * 384 + 128 + h * 32];
        float acc = 0.f;
        #pragma unroll
        for (int d = 0; d < 8; d++) {
            float4 kk = kp[d];
            acc += q[d].x * kk.x + q[d].y * kk.y + q[d].z * kk.z + q[d].w * kk.w;
        }
        int dy = (r >> 2) - (m >> 2) + 3;
        int dx = (r & 3)  - (m & 3)  + 3;
        acc += __ldg(&btbl[(dy * 7 + dx) * 4 + h]);
        sc[m] = acc;
        mx = fmaxf(mx, acc);
    }

    float sum = 0.f;
    #pragma unroll
    for (int m = 0; m < 16; m++) { sc[m] = __expf(sc[m] - mx); sum += sc[m]; }
    const float inv = 1.f / sum;

    float4 o[8];
    #pragma unroll
    for (int d = 0; d < 8; d++) o[d] = make_float4(0.f, 0.f, 0.f, 0.f);
    #pragma unroll
    for (int m = 0; m < 16; m++) {
        float p = sc[m] * inv;
        const float4* vp = (const float4*)&base[m * 384 + 256 + h * 32];
        #pragma unroll
        for (int d = 0; d < 8; d++) {
            float4 vv = vp[d];
            o[d].x += p * vv.x; o[d].y += p * vv.y; o[d].z += p * vv.z; o[d].w += p * vv.w;
        }
    }

    float4* op = (float4*)&g_att[(size_t)((w0 + lw) * 16 + r) * 128 + h * 32];
    #pragma unroll
    for (int d = 0; d < 8; d++) op[d] = o[d];
}

// ---------------------------------------------------------------------------
// inputs: 0:x 1:H 2:W 3:qkv_w 4:qkv_b 5:proj_w 6:proj_b 7:bias_tbl
// ---------------------------------------------------------------------------
extern "C" void kernel_launch(void* const* d_in, const int* in_sizes, int n_in,
                              void* d_out, int out_size) {
    const float* x     = (const float*)d_in[0];
    const float* qkvw  = (const float*)d_in[3];
    const float* qkvb  = (const float*)d_in[4];
    const float* projw = (const float*)d_in[5];
    const float* projb = (const float*)d_in[6];
    const float* btbl  = (const float*)d_in[7];
    float* out = (float*)d_out;

    const int smem = (2 * 128 * PITCH + 2 * 64 * PITCH) * 4;  // 104448 B
    cudaFuncSetAttribute(k_qkv,  cudaFuncAttributeMaxDynamicSharedMemorySize, smem);
    cudaFuncSetAttribute(k_proj, cudaFuncAttributeMaxDynamicSharedMemorySize, smem);

    k_qkv <<<dim3(QKVN / 64, ROWS / 128), 128, smem>>>(x, qkvw, qkvb);
    k_attn<<<NWIN / 2, 128>>>(btbl);
    k_proj<<<dim3(CDIM / 64, ROWS / 128), 128, smem>>>(projw, projb, out);
}

// round 4
// speedup vs baseline: 1.8767x; 1.3549x over previous
#include <cuda_runtime.h>
#include <cuda_bf16.h>
#include <cstdint>

// ---------------------------------------------------------------------------
// WindowAttention (Swin), B=16, H=W=128, C=128, WS=4, HEADS=4, hd=32
//  k_prep_x : gather x to window order, split fp32 -> bf16 hi/lo
//  k_prep_w : transpose+split weights to [n][k] bf16 hi/lo
//  k_qkv    : bf16x3 tensor GEMM (cp.async 2-stage), 128x64 tiles -> g_qkv fp32
//  k_attn   : per-window attention, writes result as bf16 hi/lo
//  k_proj   : bf16x3 tensor GEMM, scatter epilogue -> out
// ---------------------------------------------------------------------------

#define NWIN   16384
#define ROWS   (NWIN * 16)     // 262144
#define CDIM   128
#define QKVN   384

__device__ __align__(16) float g_qkv[(size_t)ROWS * QKVN];
__device__ __align__(16) __nv_bfloat16 g_xh[(size_t)ROWS * CDIM];
__device__ __align__(16) __nv_bfloat16 g_xl[(size_t)ROWS * CDIM];
__device__ __align__(16) __nv_bfloat16 g_ah[(size_t)ROWS * CDIM];
__device__ __align__(16) __nv_bfloat16 g_al[(size_t)ROWS * CDIM];
__device__ __align__(16) __nv_bfloat16 g_wqh[QKVN * CDIM];   // [n][k]
__device__ __align__(16) __nv_bfloat16 g_wql[QKVN * CDIM];
__device__ __align__(16) __nv_bfloat16 g_wph[CDIM * CDIM];
__device__ __align__(16) __nv_bfloat16 g_wpl[CDIM * CDIM];

__device__ __forceinline__ int map_row(int wr) {
    int wid = wr >> 4, t = wr & 15;
    int b   = wid >> 10, rem = wid & 1023;
    int hn  = rem >> 5,  wn  = rem & 31;
    int gy  = (hn << 2) + (t >> 2);
    int gx  = (wn << 2) + (t & 3);
    return (b << 14) + (gy << 7) + gx;
}

__device__ __forceinline__ uint32_t pk(__nv_bfloat16 a, __nv_bfloat16 b) {
    uint16_t ua = *(uint16_t*)&a, ub = *(uint16_t*)&b;
    return (uint32_t)ua | ((uint32_t)ub << 16);
}
__device__ __forceinline__ void split1(float x, __nv_bfloat16& h, __nv_bfloat16& l) {
    h = __float2bfloat16_rn(x);
    l = __float2bfloat16_rn(x - __bfloat162float(h));
}

// ---------------- prep kernels ---------------------------------------------
__global__ __launch_bounds__(256) void k_prep_x(const float* __restrict__ x) {
    int idx = blockIdx.x * 256 + threadIdx.x;          // ROWS*32 total
    int row = idx >> 5, q = idx & 31;
    float4 v = *(const float4*)&x[(size_t)map_row(row) * CDIM + q * 4];
    __nv_bfloat16 h0,l0,h1,l1,h2,l2,h3,l3;
    split1(v.x,h0,l0); split1(v.y,h1,l1); split1(v.z,h2,l2); split1(v.w,h3,l3);
    uint2 hi = make_uint2(pk(h0,h1), pk(h2,h3));
    uint2 lo = make_uint2(pk(l0,l1), pk(l2,l3));
    ((uint2*)g_xh)[idx] = hi;
    ((uint2*)g_xl)[idx] = lo;
}

__global__ __launch_bounds__(256) void k_prep_w(const float* __restrict__ wq,
                                                const float* __restrict__ wp) {
    int idx = blockIdx.x * 256 + threadIdx.x;          // 65536 total
    if (idx < QKVN * CDIM) {
        int n = idx >> 7, k = idx & 127;
        __nv_bfloat16 h, l; split1(wq[(size_t)k * QKVN + n], h, l);
        g_wqh[idx] = h; g_wql[idx] = l;
    } else {
        int j = idx - QKVN * CDIM;
        int n = j >> 7, k = j & 127;
        __nv_bfloat16 h, l; split1(wp[(size_t)k * CDIM + n], h, l);
        g_wph[j] = h; g_wpl[j] = l;
    }
}

// ---------------- GEMM -----------------------------------------------------
#define LDSM4(R, addr) \
    asm volatile("ldmatrix.sync.aligned.m8n8.x4.shared.b16 {%0,%1,%2,%3}, [%4];" \
                 : "=r"((R)[0]), "=r"((R)[1]), "=r"((R)[2]), "=r"((R)[3]) : "r"(addr))
#define MMA16816(C, A, B) \
    asm volatile("mma.sync.aligned.m16n8k16.row.col.f32.bf16.bf16.f32 " \
                 "{%0,%1,%2,%3}, {%4,%5,%6,%7}, {%8,%9}, {%0,%1,%2,%3};" \
                 : "+f"((C)[0]), "+f"((C)[1]), "+f"((C)[2]), "+f"((C)[3]) \
                 : "r"((A)[0]), "r"((A)[1]), "r"((A)[2]), "r"((A)[3]), \
                   "r"((B)[0]), "r"((B)[1]))
#define CP16(s, g) \
    asm volatile("cp.async.cg.shared.global [%0], [%1], 16;" :: "r"(s), "l"(g))
#define CP_COMMIT asm volatile("cp.async.commit_group;")

// smem stage layout (bytes): Ah[128x80] Al[128x80] Bh[64x80] Bl[64x80]
#define SOFF_AL 10240
#define SOFF_BH 20480
#define SOFF_BL 25600
#define STAGE   30720
#define SMEMSZ  (2 * STAGE)

__device__ __forceinline__ void load_stage(
        uint32_t sbase, int buf,
        const __nv_bfloat16* Ah, const __nv_bfloat16* Al,
        const __nv_bfloat16* Bh, const __nv_bfloat16* Bl,
        int m0, int n0, int ks, int t) {
    uint32_t s0 = sbase + buf * STAGE;
    int r  = t >> 2;
    int cb = (t & 3) * 16;
    #pragma unroll
    for (int h = 0; h < 4; h++) {
        int row = r + h * 32;
        size_t g = ((size_t)(m0 + row) * CDIM + ks * 32) * 2 + cb;
        CP16(s0 +           row * 80 + cb, (const char*)Ah + g);
        CP16(s0 + SOFF_AL + row * 80 + cb, (const char*)Al + g);
    }
    #pragma unroll
    for (int h = 0; h < 2; h++) {
        int row = r + h * 32;
        size_t g = ((size_t)(n0 + row) * CDIM + ks * 32) * 2 + cb;
        CP16(s0 + SOFF_BH + row * 80 + cb, (const char*)Bh + g);
        CP16(s0 + SOFF_BL + row * 80 + cb, (const char*)Bl + g);
    }
}

template <bool SCATTER>
__device__ __forceinline__ void gemm128x64(
        const __nv_bfloat16* Ah, const __nv_bfloat16* Al,
        const __nv_bfloat16* Bh, const __nv_bfloat16* Bl,
        const float* __restrict__ bias, float* __restrict__ Out, int ldo,
        int m0, int n0) {
    extern __shared__ char smem[];
    uint32_t sbase = (uint32_t)__cvta_generic_to_shared(smem);
    const int t = threadIdx.x, lane = t & 31, wid = t >> 5;
    const int row0 = wid * 32;

    load_stage(sbase, 0, Ah, Al, Bh, Bl, m0, n0, 0, t); CP_COMMIT;
    load_stage(sbase, 1, Ah, Al, Bh, Bl, m0, n0, 1, t); CP_COMMIT;

    float acc[2][8][4];
    #pragma unroll
    for (int i = 0; i < 2; i++)
        #pragma unroll
        for (int j = 0; j < 8; j++)
            #pragma unroll
            for (int c = 0; c < 4; c++) acc[i][j][c] = 0.f;

    const uint32_t a_row = lane & 15;
    const uint32_t a_cb  = (lane >> 4) * 16;
    const uint32_t b_row = (lane & 7) + ((lane >> 4) << 3);
    const uint32_t b_cb  = ((lane >> 3) & 1) * 16;

    #pragma unroll
    for (int ks = 0; ks < 4; ks++) {
        const int buf = ks & 1;
        if (ks < 3) asm volatile("cp.async.wait_group 1;");
        else        asm volatile("cp.async.wait_group 0;");
        __syncthreads();
        uint32_t s0 = sbase + buf * STAGE;

        #pragma unroll
        for (int kk = 0; kk < 2; kk++) {
            uint32_t ah[2][4], al2[2][4], bh[4][4], bl[4][4];
            #pragma unroll
            for (int mi = 0; mi < 2; mi++) {
                uint32_t ad = s0 + (row0 + mi * 16 + a_row) * 80 + kk * 32 + a_cb;
                LDSM4(ah[mi],  ad);
                LDSM4(al2[mi], ad + SOFF_AL);
            }
            #pragma unroll
            for (int g = 0; g < 4; g++) {
                uint32_t bd = s0 + SOFF_BH + (g * 16 + b_row) * 80 + kk * 32 + b_cb;
                LDSM4(bh[g], bd);
                LDSM4(bl[g], bd + (SOFF_BL - SOFF_BH));
            }
            #pragma unroll
            for (int mi = 0; mi < 2; mi++)
                #pragma unroll
                for (int n8 = 0; n8 < 8; n8++) {
                    uint32_t* BH = &bh[n8 >> 1][(n8 & 1) * 2];
                    uint32_t* BL = &bl[n8 >> 1][(n8 & 1) * 2];
                    MMA16816(acc[mi][n8], ah[mi],  BH);
                    MMA16816(acc[mi][n8], ah[mi],  BL);
                    MMA16816(acc[mi][n8], al2[mi], BH);
                }
        }
        __syncthreads();
        if (ks + 2 < 4) {
            load_stage(sbase, buf, Ah, Al, Bh, Bl, m0, n0, ks + 2, t);
            CP_COMMIT;
        }
    }

    #pragma unroll
    for (int mi = 0; mi < 2; mi++) {
        #pragma unroll
        for (int n8 = 0; n8 < 8; n8++) {
            int r = m0 + row0 + mi * 16 + (lane >> 2);
            int c = n0 + n8 * 8 + (lane & 3) * 2;
            float b0 = __ldg(&bias[c]), b1 = __ldg(&bias[c + 1]);
            int r0g = SCATTER ? map_row(r)     : r;
            int r1g = SCATTER ? map_row(r + 8) : (r + 8);
            *(float2*)&Out[(size_t)r0g * ldo + c] =
                make_float2(acc[mi][n8][0] + b0, acc[mi][n8][1] + b1);
            *(float2*)&Out[(size_t)r1g * ldo + c] =
                make_float2(acc[mi][n8][2] + b0, acc[mi][n8][3] + b1);
        }
    }
}

__global__ __launch_bounds__(128) void k_qkv(const float* __restrict__ bias) {
    gemm128x64<false>(g_xh, g_xl, g_wqh, g_wql, bias, g_qkv, QKVN,
                      blockIdx.y * 128, blockIdx.x * 64);
}

__global__ __launch_bounds__(128) void k_proj(const float* __restrict__ bias,
                                              float* __restrict__ out) {
    gemm128x64<true>(g_ah, g_al, g_wph, g_wpl, bias, out, CDIM,
                     blockIdx.y * 128, blockIdx.x * 64);
}

// ---------------- attention ------------------------------------------------
__global__ __launch_bounds__(128) void k_attn(const float* __restrict__ btbl) {
    __shared__ float s[2 * 16 * 384];

    const int tid = threadIdx.x;
    const int w0  = blockIdx.x * 2;

    {
        const float4* src = (const float4*)&g_qkv[(size_t)w0 * (16 * 384)];
        float4* dst = (float4*)s;
        #pragma unroll
        for (int i = 0; i < 24; i++) dst[i * 128 + tid] = src[i * 128 + tid];
    }
    __syncthreads();

    const int lw = tid >> 6;
    const int h  = (tid >> 4) & 3;
    const int r  = tid & 15;
    const float scale = 0.17677669529663687f;
    float* base = s + lw * 6144;

    float4 q[8];
    {
        const float4* qp = (const float4*)&base[r * 384 + h * 32];
        #pragma unroll
        for (int d = 0; d < 8; d++) {
            q[d] = qp[d];
            q[d].x *= scale; q[d].y *= scale; q[d].z *= scale; q[d].w *= scale;
        }
    }

    float sc[16];
    float mx = -1e30f;
    #pragma unroll
    for (int m = 0; m < 16; m++) {
        const float4* kp = (const float4*)&base[m * 384 + 128 + h * 32];
        float acc = 0.f;
        #pragma unroll
        for (int d = 0; d < 8; d++) {
            float4 kk = kp[d];
            acc += q[d].x * kk.x + q[d].y * kk.y + q[d].z * kk.z + q[d].w * kk.w;
        }
        int dy = (r >> 2) - (m >> 2) + 3;
        int dx = (r & 3)  - (m & 3)  + 3;
        acc += __ldg(&btbl[(dy * 7 + dx) * 4 + h]);
        sc[m] = acc;
        mx = fmaxf(mx, acc);
    }

    float sum = 0.f;
    #pragma unroll
    for (int m = 0; m < 16; m++) { sc[m] = __expf(sc[m] - mx); sum += sc[m]; }
    const float inv = 1.f / sum;

    float4 o[8];
    #pragma unroll
    for (int d = 0; d < 8; d++) o[d] = make_float4(0.f, 0.f, 0.f, 0.f);
    #pragma unroll
    for (int m = 0; m < 16; m++) {
        float p = sc[m] * inv;
        const float4* vp = (const float4*)&base[m * 384 + 256 + h * 32];
        #pragma unroll
        for (int d = 0; d < 8; d++) {
            float4 vv = vp[d];
            o[d].x += p * vv.x; o[d].y += p * vv.y; o[d].z += p * vv.z; o[d].w += p * vv.w;
        }
    }

    // write result as bf16 hi/lo (proj GEMM A operand)
    size_t rowbase = (size_t)((w0 + lw) * 16 + r) * 128 + h * 32;
    #pragma unroll
    for (int d = 0; d < 8; d++) {
        __nv_bfloat16 h0,l0,h1,l1,h2,l2,h3,l3;
        split1(o[d].x,h0,l0); split1(o[d].y,h1,l1);
        split1(o[d].z,h2,l2); split1(o[d].w,h3,l3);
        ((uint2*)g_ah)[(rowbase >> 2) + d] = make_uint2(pk(h0,h1), pk(h2,h3));
        ((uint2*)g_al)[(rowbase >> 2) + d] = make_uint2(pk(l0,l1), pk(l2,l3));
    }
}

// ---------------------------------------------------------------------------
// inputs: 0:x 1:H 2:W 3:qkv_w 4:qkv_b 5:proj_w 6:proj_b 7:bias_tbl
// ---------------------------------------------------------------------------
extern "C" void kernel_launch(void* const* d_in, const int* in_sizes, int n_in,
                              void* d_out, int out_size) {
    const float* x     = (const float*)d_in[0];
    const float* qkvw  = (const float*)d_in[3];
    const float* qkvb  = (const float*)d_in[4];
    const float* projw = (const float*)d_in[5];
    const float* projb = (const float*)d_in[6];
    const float* btbl  = (const float*)d_in[7];
    float* out = (float*)d_out;

    cudaFuncSetAttribute(k_qkv,  cudaFuncAttributeMaxDynamicSharedMemorySize, SMEMSZ);
    cudaFuncSetAttribute(k_proj, cudaFuncAttributeMaxDynamicSharedMemorySize, SMEMSZ);

    k_prep_x<<<ROWS * 32 / 256, 256>>>(x);
    k_prep_w<<<(QKVN * CDIM + CDIM * CDIM) / 256, 256>>>(qkvw, projw);
    k_qkv <<<dim3(QKVN / 64, ROWS / 128), 128, SMEMSZ>>>(qkvb);
    k_attn<<<NWIN / 2, 128>>>(btbl);
    k_proj<<<dim3(CDIM / 64, ROWS / 128), 128, SMEMSZ>>>(projb, out);
}